// round 17
// baseline (speedup 1.0000x reference)
#include <cuda_runtime.h>

#define Bsz 4096
#define Lsz 512
#define Msz 17
#define Hsz 17
#define Tch 4
#define NCHUNK (Lsz / Tch)          // 128
#define PAIR_B 7                    // thread-rows per block; each thread owns 2 rows
#define ROWS_B (2 * PAIR_B)         // 14 rows per block
#define NTHREADS (PAIR_B * Hsz)     // 119 -> 2 blocks/SM, 28 rows/SM, ~275 regs/thread budget
#define NBLOCKS ((Bsz + ROWS_B - 1) / ROWS_B)  // 293
#define ROW_STRIDE (Lsz * Msz)
#define OROW_STRIDE (Lsz * Hsz)

typedef unsigned long long u64;

__device__ __forceinline__ u64 pk2(float a, float b) {
    u64 r; asm("mov.b64 %0, {%1, %2};" : "=l"(r) : "f"(a), "f"(b)); return r;
}
__device__ __forceinline__ void upk2(u64 v, float &a, float &b) {
    asm("mov.b64 {%0, %1}, %2;" : "=f"(a), "=f"(b) : "l"(v));
}
__device__ __forceinline__ void ffma2(u64 &d, u64 a, u64 b) {
    asm("fma.rn.f32x2 %0, %1, %2, %0;" : "+l"(d) : "l"(a), "l"(b));
}
__device__ __forceinline__ float tanh_ap(float z) {
    float r; asm("tanh.approx.f32 %0, %1;" : "=f"(r) : "f"(z)); return r;
}

__global__ __launch_bounds__(NTHREADS, 2) void lstm_fused_kernel(
    const float* __restrict__ x,
    const float* __restrict__ Wih,
    const float* __restrict__ Whh,
    const float* __restrict__ bih,
    const float* __restrict__ bhh,
    float* __restrict__ out)
{
    __shared__ __align__(16) ulonglong2 wih_s[Msz * Hsz];   // {if,go} pairs
    __shared__ __align__(16) float sx[ROWS_B][Tch * Msz];   // x chunks, plain, [k*4+t]
    __shared__ __align__(16) float shp[2][ROWS_B][20];      // h states, plain, dbl-buf

    const int tid = threadIdx.x;
    const int j = tid % Hsz;
    const int y = tid / Hsz;            // 0..6 ; rows y and y+7
    const int r0 = blockIdx.x * ROWS_B + y;
    const int r1 = r0 + PAIR_B;
    const bool act0 = (r0 < Bsz);
    const bool act1 = (r1 < Bsz);
    const int bb0 = act0 ? r0 : (Bsz - 1);
    const int bb1 = act1 ? r1 : (Bsz - 1);

    // ---- W_ih into smem; sigmoid gates (i,f,o) pre-scaled by 0.5 ----
    for (int idx = tid; idx < Msz * Hsz; idx += NTHREADS) {
        int k = idx / Hsz, jj = idx % Hsz;
        ulonglong2 w2;
        w2.x = pk2(0.5f * Wih[jj * Msz + k],
                   0.5f * Wih[(Hsz + jj) * Msz + k]);
        w2.y = pk2(Wih[(2 * Hsz + jj) * Msz + k],
                   0.5f * Wih[(3 * Hsz + jj) * Msz + k]);
        wih_s[idx] = w2;
    }

    // ---- W_hh in registers (shared by both rows): 8 pairs/gate + scalar k16 ----
    u64 wh0[8], wh1[8], wh2[8], wh3[8];
    float w16_0, w16_1, w16_2, w16_3;
    {
        const float* w0 = Whh + (0 * Hsz + j) * Hsz;
        const float* w1 = Whh + (1 * Hsz + j) * Hsz;
        const float* w2 = Whh + (2 * Hsz + j) * Hsz;
        const float* w3 = Whh + (3 * Hsz + j) * Hsz;
#pragma unroll
        for (int p = 0; p < 8; p++) {
            wh0[p] = pk2(0.5f * w0[2 * p], 0.5f * w0[2 * p + 1]);
            wh1[p] = pk2(0.5f * w1[2 * p], 0.5f * w1[2 * p + 1]);
            wh2[p] = pk2(w2[2 * p],        w2[2 * p + 1]);
            wh3[p] = pk2(0.5f * w3[2 * p], 0.5f * w3[2 * p + 1]);
        }
        w16_0 = 0.5f * w0[16];
        w16_1 = 0.5f * w1[16];
        w16_2 = w2[16];
        w16_3 = 0.5f * w3[16];
    }
    const u64 b_if = pk2(0.5f * (bih[j] + bhh[j]),
                         0.5f * (bih[Hsz + j] + bhh[Hsz + j]));
    const u64 b_go = pk2(bih[2 * Hsz + j] + bhh[2 * Hsz + j],
                         0.5f * (bih[3 * Hsz + j] + bhh[3 * Hsz + j]));

    const long OUT_ELEMS = (long)Bsz * Lsz * Hsz;
    const long H_OFF = OUT_ELEMS;
    const long C_OFF = OUT_ELEMS + (long)Bsz * Hsz;
    const long X_OFF = OUT_ELEMS + 2L * (long)Bsz * Hsz;

    const float4* xr0 = (const float4*)(x + (long)bb0 * ROW_STRIDE);
    const float4* xr1 = (const float4*)(x + (long)bb1 * ROW_STRIDE);
    float4* xo0 = (float4*)(out + X_OFF + (long)bb0 * ROW_STRIDE);
    float4* xo1 = (float4*)(out + X_OFF + (long)bb1 * ROW_STRIDE);
    float* ob0 = out + (long)bb0 * OROW_STRIDE;
    float* ob1 = out + (long)bb1 * OROW_STRIDE;

    shp[0][y][j] = 0.0f;          shp[1][y][j] = 0.0f;
    shp[0][y + PAIR_B][j] = 0.0f; shp[1][y + PAIR_B][j] = 0.0f;
    float c0 = 0.0f, hn0 = 0.0f, c1 = 0.0f, hn1 = 0.0f;

    float4 v0 = xr0[j];
    float4 v1 = xr1[j];

    for (int ch = 0; ch < NCHUNK; ch++) {
        const int t0 = ch * Tch;

        // ---- stage both rows' chunks + mirror to x passthrough ----
        if (act0) xo0[ch * Msz + j] = v0;
        if (act1) xo1[ch * Msz + j] = v1;
        {
            float f0[4] = {v0.x, v0.y, v0.z, v0.w};
            float f1[4] = {v1.x, v1.y, v1.z, v1.w};
#pragma unroll
            for (int i = 0; i < 4; i++) {
                int fi = 4 * j + i;
                int t = fi / Msz, k = fi - Msz * t;
                sx[y][k * Tch + t] = f0[i];
                sx[y + PAIR_B][k * Tch + t] = f1[i];
            }
        }
        if (ch + 1 < NCHUNK) {
            v0 = xr0[(ch + 1) * Msz + j];
            v1 = xr1[(ch + 1) * Msz + j];
        }
        __syncthreads();

        // ---- 4-step x-projection burst for BOTH rows (weight LDS shared) ----
        u64 ai0[Tch], ag0[Tch], ai1[Tch], ag1[Tch];
#pragma unroll
        for (int t = 0; t < Tch; t++) {
            ai0[t] = b_if; ag0[t] = b_go;
            ai1[t] = b_if; ag1[t] = b_go;
        }
#pragma unroll
        for (int k = 0; k < Msz; k++) {
            const ulonglong2 w2 = wih_s[k * Hsz + j];
            const float4 xa = *(const float4*)&sx[y][k * Tch];
            const float4 xb = *(const float4*)&sx[y + PAIR_B][k * Tch];
            const u64 a0 = pk2(xa.x, xa.x);
            const u64 a1 = pk2(xa.y, xa.y);
            const u64 a2 = pk2(xa.z, xa.z);
            const u64 a3 = pk2(xa.w, xa.w);
            const u64 e0 = pk2(xb.x, xb.x);
            const u64 e1 = pk2(xb.y, xb.y);
            const u64 e2 = pk2(xb.z, xb.z);
            const u64 e3 = pk2(xb.w, xb.w);
            ffma2(ai0[0], w2.x, a0); ffma2(ag0[0], w2.y, a0);
            ffma2(ai1[0], w2.x, e0); ffma2(ag1[0], w2.y, e0);
            ffma2(ai0[1], w2.x, a1); ffma2(ag0[1], w2.y, a1);
            ffma2(ai1[1], w2.x, e1); ffma2(ag1[1], w2.y, e1);
            ffma2(ai0[2], w2.x, a2); ffma2(ag0[2], w2.y, a2);
            ffma2(ai1[2], w2.x, e2); ffma2(ag1[2], w2.y, e2);
            ffma2(ai0[3], w2.x, a3); ffma2(ag0[3], w2.y, a3);
            ffma2(ai1[3], w2.x, e3); ffma2(ag1[3], w2.y, e3);
        }

        // ---- 4 recurrence steps, two rows per step, fully interleaved ----
#pragma unroll
        for (int tl = 0; tl < Tch; tl++) {
            const int t = t0 + tl;
            const int cur = t & 1, nxt = cur ^ 1;

            const ulonglong2* hpA = (const ulonglong2*)shp[cur][y];
            const ulonglong2* hpB = (const ulonglong2*)shp[cur][y + PAIR_B];
            const ulonglong2 A0 = hpA[0], A1 = hpA[1], A2 = hpA[2], A3 = hpA[3];
            const ulonglong2 B0 = hpB[0], B1 = hpB[1], B2 = hpB[2], B3 = hpB[3];
            const float hA16 = shp[cur][y][16];
            const float hB16 = shp[cur][y + PAIR_B][16];

            // independent accumulator sets for the two rows -> ptxas can interleave
            u64 pa0 = 0ULL, pa1 = 0ULL, pa2 = 0ULL, pa3 = 0ULL;
            u64 qb0 = 0ULL, qb1 = 0ULL, qb2 = 0ULL, qb3 = 0ULL;

            ffma2(pa0, wh0[0], A0.x); ffma2(pa1, wh1[0], A0.x);
            ffma2(pa2, wh2[0], A0.x); ffma2(pa3, wh3[0], A0.x);
            ffma2(qb0, wh0[0], B0.x); ffma2(qb1, wh1[0], B0.x);
            ffma2(qb2, wh2[0], B0.x); ffma2(qb3, wh3[0], B0.x);
            ffma2(pa0, wh0[1], A0.y); ffma2(pa1, wh1[1], A0.y);
            ffma2(pa2, wh2[1], A0.y); ffma2(pa3, wh3[1], A0.y);
            ffma2(qb0, wh0[1], B0.y); ffma2(qb1, wh1[1], B0.y);
            ffma2(qb2, wh2[1], B0.y); ffma2(qb3, wh3[1], B0.y);
            ffma2(pa0, wh0[2], A1.x); ffma2(pa1, wh1[2], A1.x);
            ffma2(pa2, wh2[2], A1.x); ffma2(pa3, wh3[2], A1.x);
            ffma2(qb0, wh0[2], B1.x); ffma2(qb1, wh1[2], B1.x);
            ffma2(qb2, wh2[2], B1.x); ffma2(qb3, wh3[2], B1.x);
            ffma2(pa0, wh0[3], A1.y); ffma2(pa1, wh1[3], A1.y);
            ffma2(pa2, wh2[3], A1.y); ffma2(pa3, wh3[3], A1.y);
            ffma2(qb0, wh0[3], B1.y); ffma2(qb1, wh1[3], B1.y);
            ffma2(qb2, wh2[3], B1.y); ffma2(qb3, wh3[3], B1.y);
            ffma2(pa0, wh0[4], A2.x); ffma2(pa1, wh1[4], A2.x);
            ffma2(pa2, wh2[4], A2.x); ffma2(pa3, wh3[4], A2.x);
            ffma2(qb0, wh0[4], B2.x); ffma2(qb1, wh1[4], B2.x);
            ffma2(qb2, wh2[4], B2.x); ffma2(qb3, wh3[4], B2.x);
            ffma2(pa0, wh0[5], A2.y); ffma2(pa1, wh1[5], A2.y);
            ffma2(pa2, wh2[5], A2.y); ffma2(pa3, wh3[5], A2.y);
            ffma2(qb0, wh0[5], B2.y); ffma2(qb1, wh1[5], B2.y);
            ffma2(qb2, wh2[5], B2.y); ffma2(qb3, wh3[5], B2.y);
            ffma2(pa0, wh0[6], A3.x); ffma2(pa1, wh1[6], A3.x);
            ffma2(pa2, wh2[6], A3.x); ffma2(pa3, wh3[6], A3.x);
            ffma2(qb0, wh0[6], B3.x); ffma2(qb1, wh1[6], B3.x);
            ffma2(qb2, wh2[6], B3.x); ffma2(qb3, wh3[6], B3.x);
            ffma2(pa0, wh0[7], A3.y); ffma2(pa1, wh1[7], A3.y);
            ffma2(pa2, wh2[7], A3.y); ffma2(pa3, wh3[7], A3.y);
            ffma2(qb0, wh0[7], B3.y); ffma2(qb1, wh1[7], B3.y);
            ffma2(qb2, wh2[7], B3.y); ffma2(qb3, wh3[7], B3.y);

            float xi0, xf0, xg0, xo0_, xi1, xf1, xg1, xo1_;
            upk2(ai0[tl], xi0, xf0);
            upk2(ag0[tl], xg0, xo0_);
            upk2(ai1[tl], xi1, xf1);
            upk2(ag1[tl], xg1, xo1_);
            float l, h;
            upk2(pa0, l, h); const float zi0 = fmaf(w16_0, hA16, xi0  + (l + h));
            upk2(pa1, l, h); const float zf0 = fmaf(w16_1, hA16, xf0  + (l + h));
            upk2(pa2, l, h); const float zg0 = fmaf(w16_2, hA16, xg0  + (l + h));
            upk2(pa3, l, h); const float zo0 = fmaf(w16_3, hA16, xo0_ + (l + h));
            upk2(qb0, l, h); const float zi1 = fmaf(w16_0, hB16, xi1  + (l + h));
            upk2(qb1, l, h); const float zf1 = fmaf(w16_1, hB16, xf1  + (l + h));
            upk2(qb2, l, h); const float zg1 = fmaf(w16_2, hB16, xg1  + (l + h));
            upk2(qb3, l, h); const float zo1 = fmaf(w16_3, hB16, xo1_ + (l + h));

            const float ig0 = fmaf(0.5f, tanh_ap(zi0), 0.5f);
            const float ig1 = fmaf(0.5f, tanh_ap(zi1), 0.5f);
            const float fg0 = fmaf(0.5f, tanh_ap(zf0), 0.5f);
            const float fg1 = fmaf(0.5f, tanh_ap(zf1), 0.5f);
            const float gg0 = tanh_ap(zg0);
            const float gg1 = tanh_ap(zg1);
            const float og0 = fmaf(0.5f, tanh_ap(zo0), 0.5f);
            const float og1 = fmaf(0.5f, tanh_ap(zo1), 0.5f);
            c0  = fg0 * c0 + ig0 * gg0;
            c1  = fg1 * c1 + ig1 * gg1;
            hn0 = og0 * tanh_ap(c0);
            hn1 = og1 * tanh_ap(c1);

            if (act0) ob0[t * Hsz + j] = hn0;
            if (act1) ob1[t * Hsz + j] = hn1;
            shp[nxt][y][j] = hn0;
            shp[nxt][y + PAIR_B][j] = hn1;
            __syncthreads();
        }
    }

    if (act0) {
        out[H_OFF + (long)r0 * Hsz + j] = hn0;
        out[C_OFF + (long)r0 * Hsz + j] = c0;
    }
    if (act1) {
        out[H_OFF + (long)r1 * Hsz + j] = hn1;
        out[C_OFF + (long)r1 * Hsz + j] = c1;
    }
}

extern "C" void kernel_launch(void* const* d_in, const int* in_sizes, int n_in,
                              void* d_out, int out_size) {
    const float* x   = (const float*)d_in[0];
    const float* Wih = (const float*)d_in[1];
    const float* Whh = (const float*)d_in[2];
    const float* bih = (const float*)d_in[3];
    const float* bhh = (const float*)d_in[4];
    float* out = (float*)d_out;
    (void)in_sizes; (void)n_in; (void)out_size;

    lstm_fused_kernel<<<NBLOCKS, NTHREADS>>>(x, Wih, Whh, bih, bhh, out);
}